// round 16
// baseline (speedup 1.0000x reference)
#include <cuda_runtime.h>
#include <math.h>
#include <float.h>

#define NB   8
#define ND   1024
#define NHH  16
#define HDm  64
#define HW   4096
#define NS   4097   // 1 CLS + 4096 tokens
#define SST  4100   // scores row stride, multiple of 4 -> float4-aligned rows

typedef unsigned long long u64;

// ---------------- packed f32x2 helpers ----------------
__device__ __forceinline__ u64 pack2(float lo, float hi) {
    u64 r; asm("mov.b64 %0, {%1,%2};" : "=l"(r) : "f"(lo), "f"(hi)); return r;
}
__device__ __forceinline__ void unpack2(u64 v, float& lo, float& hi) {
    asm("mov.b64 {%0,%1}, %2;" : "=f"(lo), "=f"(hi) : "l"(v));
}
__device__ __forceinline__ void fma2(u64& d, u64 a, u64 b) {
    asm("fma.rn.f32x2 %0, %1, %2, %0;" : "+l"(d) : "l"(a), "l"(b));
}
__device__ __forceinline__ u64 fma2n(u64 a, u64 b, u64 c) {
    u64 d; asm("fma.rn.f32x2 %0, %1, %2, %3;" : "=l"(d) : "l"(a), "l"(b), "l"(c)); return d;
}
__device__ __forceinline__ u64 add2(u64 a, u64 b) {
    u64 d; asm("add.rn.f32x2 %0, %1, %2;" : "=l"(d) : "l"(a), "l"(b)); return d;
}
__device__ __forceinline__ u64 mul2(u64 a, u64 b) {
    u64 d; asm("mul.rn.f32x2 %0, %1, %2;" : "=l"(d) : "l"(a), "l"(b)); return d;
}
__device__ __forceinline__ u64 ldg2(const float* p) { return __ldg((const u64*)p); }

// ---------------- scratch (device globals; no allocations) ----------------
__device__ float g_pe[ND * HW];           // [d][p] positional encoding (16 MB)
__device__ float g_q0[NB * ND];
__device__ float g_kcls[NB * ND];
__device__ float g_vcls[NB * ND];
__device__ float g_u[NB * ND * NHH];      // [b][d][h]
__device__ u64   g_t2[NB * ND];           // t_b duplicated (t,t)
__device__ float g_ck[NB * NHH];
__device__ float g_scores[NB * NHH * SST];// padded rows (16B-aligned)
__device__ float g_probsT[NB * NHH * HW]; // [b][h][token] (token = s-1)
__device__ float g_pcls[NB * NHH];        // prob of s=0 (CLS)
__device__ float g_nmu[NB * HW];          // -mu per token
__device__ float g_rs[NB * HW];           // rsqrt(var+eps) per token
__device__ float g_m[NB * NHH * ND];
__device__ float g_clsout[NB * ND];
__device__ float g_resid[NB * ND];

// ---------------- kPre: PE table (blocks 0..1023) + P1 GEMV (1024..1407) ----
__global__ void __launch_bounds__(256) kPre(const float* __restrict__ Wqkv,
                                            const float* __restrict__ bqkv,
                                            const float* __restrict__ ctx) {
    int bx = blockIdx.x;
    if (bx < ND) {
        // positional encoding row d: one sincos base per thread + 15 rotations
        int d  = bx;
        int e2 = d & ~1;
        float rate = (float)exp(-(double)e2 * (9.210340371976184 / 1024.0));
        bool iscos = (d & 1);
        int tid = threadIdx.x;
        float s, c, sd, cd;
        sincosf((float)tid * rate, &s, &c);      // base angle
        sincosf(256.f * rate, &sd, &cd);         // step = 256 tokens
        int base = d * HW + tid;
#pragma unroll
        for (int j = 0; j < 16; j++) {
            g_pe[base + j * 256] = iscos ? c : s;
            float s2 = fmaf(s, cd, c * sd);
            float c2 = fmaf(c, cd, -s * sd);
            s = s2; c = c2;
        }
    } else {
        // P1: q0 / k_cls / v_cls (warp per Wqkv row)
        int gw   = (bx - ND) * 8 + (threadIdx.x >> 5);
        int lane = threadIdx.x & 31;
        if (gw >= 3 * ND) return;
        const float* row = Wqkv + (size_t)gw * ND;
        float acc[NB];
#pragma unroll
        for (int b = 0; b < NB; b++) acc[b] = 0.f;
        for (int e = lane; e < ND; e += 32) {
            float wv = row[e];
#pragma unroll
            for (int b = 0; b < NB; b++) acc[b] += wv * ctx[b * ND + e];
        }
#pragma unroll
        for (int b = 0; b < NB; b++) {
#pragma unroll
            for (int off = 16; off; off >>= 1)
                acc[b] += __shfl_xor_sync(0xffffffffu, acc[b], off);
        }
        if (lane == 0) {
            float bias = bqkv[gw];
            float* dst;
            if (gw < ND)            dst = g_q0   + gw;
            else if (gw < 2 * ND)   dst = g_kcls + (gw - ND);
            else                    dst = g_vcls + (gw - 2 * ND);
#pragma unroll
            for (int b = 0; b < NB; b++) dst[b * ND] = acc[b] + bias;
        }
    }
}

// ---------------- P2: u (128 blocks), t2 (128 blocks), ck (1 block) ---------
__global__ void __launch_bounds__(256) kP2(const float* __restrict__ Wqkv,
                                           const float* __restrict__ bqkv,
                                           const float* __restrict__ Wo,
                                           const float* __restrict__ bo) {
    int bx = blockIdx.x;
    if (bx < 128) {
        int h   = bx >> 3;
        int dsl = bx & 7;
        __shared__ float s_q[NB * HDm];
        for (int i = threadIdx.x; i < NB * HDm; i += blockDim.x) {
            int b = i >> 6, j = i & 63;
            s_q[i] = g_q0[b * ND + h * HDm + j];
        }
        __syncthreads();
        if (threadIdx.x < 128) {
            int d = dsl * 128 + threadIdx.x;
            float acc[NB];
#pragma unroll
            for (int b = 0; b < NB; b++) acc[b] = 0.f;
#pragma unroll 4
            for (int j = 0; j < HDm; j++) {
                float wv = __ldg(Wqkv + (size_t)(ND + h * HDm + j) * ND + d);
#pragma unroll
                for (int b = 0; b < NB; b++) acc[b] += s_q[b * HDm + j] * wv;
            }
#pragma unroll
            for (int b = 0; b < NB; b++)
                g_u[(size_t)(b * ND + d) * NHH + h] = acc[b];
        }
    } else if (bx < 256) {
        int d    = (bx - 128) * 8 + (threadIdx.x >> 5);
        int lane = threadIdx.x & 31;
        const float* row = Wo + (size_t)d * ND;
        float acc[NB];
#pragma unroll
        for (int b = 0; b < NB; b++) acc[b] = 0.f;
        for (int e = lane; e < ND; e += 32) {
            float wv = row[e];
#pragma unroll
            for (int b = 0; b < NB; b++) acc[b] += wv * g_vcls[b * ND + e];
        }
#pragma unroll
        for (int b = 0; b < NB; b++) {
#pragma unroll
            for (int off = 16; off; off >>= 1)
                acc[b] += __shfl_xor_sync(0xffffffffu, acc[b], off);
        }
        if (lane == 0) {
            float bias = bo[d];
#pragma unroll
            for (int b = 0; b < NB; b++) {
                float v = acc[b] + bias;
                g_t2[b * ND + d] = pack2(v, v);
            }
        }
    } else {
        int t = threadIdx.x;
        if (t < NB * NHH) {
            int b = t >> 4, h = t & 15;
            float ck = 0.f, s0 = 0.f;
            for (int j = 0; j < HDm; j++) {
                float q = g_q0[b * ND + h * HDm + j];
                ck += q * bqkv[ND + h * HDm + j];
                s0 += q * g_kcls[b * ND + h * HDm + j];
            }
            g_ck[t] = ck;
            g_scores[(size_t)t * SST] = s0 * 0.125f;
        }
    }
}

// ---------------- kA1: scores + LayerNorm statistics ----------------
// block = (b, 64 tokens). 8 warps; warp w handles d = 8i+w; thread = 2 tokens.
// unroll 4: smem caps us at 2 blocks/SM, so registers are free -> deeper
// load batching (MLP) at zero occupancy cost.
__global__ void __launch_bounds__(256) kA1(const float* __restrict__ x) {
    int b    = blockIdx.y;
    int p0   = blockIdx.x * 64;
    int tid  = threadIdx.x;
    int w    = tid >> 5;
    int lane = tid & 31;
    int p    = p0 + lane * 2;

    __shared__ float s_acc[8][64][18];   // [warp][token][head], padded
    __shared__ float s_sum[8][64];
    __shared__ float s_sq[8][64];

    const float* xb = x   + (size_t)b * ND * HW;
    const u64*   tb = g_t2 + b * ND;
    const u64*   ub = (const u64*)(g_u + (size_t)b * ND * NHH);

    u64 acc0[8], acc1[8];   // [head-pair] for token0 / token1
#pragma unroll
    for (int i = 0; i < 8; i++) { acc0[i] = 0ull; acc1[i] = 0ull; }
    u64 lsum = 0ull, lsq = 0ull;

#pragma unroll 4
    for (int i = 0; i < 128; i++) {
        int d = i * 8 + w;
        size_t off = (size_t)d * HW + p;
        u64 xc2 = add2(ldg2(xb + off), ldg2(g_pe + off));
        u64 r2  = add2(xc2, __ldg(tb + d));
        lsum = add2(lsum, r2);
        fma2(lsq, r2, r2);
        float xl, xh; unpack2(xc2, xl, xh);
        u64 xll = pack2(xl, xl), xhh = pack2(xh, xh);
        const ulonglong2* uu = (const ulonglong2*)(ub + (size_t)d * 8);
#pragma unroll
        for (int q = 0; q < 4; q++) {
            ulonglong2 u2 = __ldg(uu + q);
            fma2(acc0[2 * q],     u2.x, xll);
            fma2(acc0[2 * q + 1], u2.y, xll);
            fma2(acc1[2 * q],     u2.x, xhh);
            fma2(acc1[2 * q + 1], u2.y, xhh);
        }
    }

#pragma unroll
    for (int hp = 0; hp < 8; hp++) {
        *(u64*)&s_acc[w][lane * 2][hp * 2]     = acc0[hp];
        *(u64*)&s_acc[w][lane * 2 + 1][hp * 2] = acc1[hp];
    }
    {
        float a, c;
        unpack2(lsum, a, c); s_sum[w][lane * 2] = a; s_sum[w][lane * 2 + 1] = c;
        unpack2(lsq,  a, c); s_sq[w][lane * 2]  = a; s_sq[w][lane * 2 + 1]  = c;
    }
    __syncthreads();

    if (tid < 64) {
        float m = 0.f, q = 0.f;
#pragma unroll
        for (int ww = 0; ww < 8; ww++) { m += s_sum[ww][tid]; q += s_sq[ww][tid]; }
        float mu  = m * (1.f / 1024.f);
        float var = q * (1.f / 1024.f) - mu * mu;
        g_nmu[b * HW + p0 + tid] = -mu;
        g_rs[b * HW + p0 + tid]  = rsqrtf(var + 1e-5f);
    }
    // scores: 1024 (h,tok) pairs
#pragma unroll
    for (int r = 0; r < 4; r++) {
        int idx = r * 256 + tid;
        int h = idx >> 6, tok = idx & 63;
        float sc = 0.f;
#pragma unroll
        for (int ww = 0; ww < 8; ww++) sc += s_acc[ww][tok][h];
        sc = (sc + __ldg(g_ck + b * NHH + h)) * 0.125f;
        g_scores[(size_t)(b * NHH + h) * SST + (p0 + tok + 1)] = sc;
    }
}

// ---------------- Softmax (row = (b,h), len 4097) -> probsT [b][h][token] ---
// Register-resident: one global read, no expf recompute.
__global__ void __launch_bounds__(256) kSM() {
    int bh = blockIdx.x;
    const float* sc = g_scores + (size_t)bh * SST;   // 16B-aligned row
    __shared__ float sred[8];
    __shared__ float sbc;
    int tid = threadIdx.x, w = tid >> 5, lane = tid & 31;

    // thread t holds s = t*16 .. t*16+15 (4 x LDG.128); tid 0 also handles s=4096
    float v[16];
    int base = tid * 16;
#pragma unroll
    for (int k = 0; k < 4; k++) {
        float4 q = __ldg((const float4*)(sc + base) + k);
        v[k * 4 + 0] = q.x; v[k * 4 + 1] = q.y; v[k * 4 + 2] = q.z; v[k * 4 + 3] = q.w;
    }
    float vtail = (tid == 0) ? sc[4096] : -FLT_MAX;

    float mx = vtail;
#pragma unroll
    for (int k = 0; k < 16; k++) mx = fmaxf(mx, v[k]);
#pragma unroll
    for (int off = 16; off; off >>= 1) mx = fmaxf(mx, __shfl_xor_sync(0xffffffffu, mx, off));
    if (lane == 0) sred[w] = mx;
    __syncthreads();
    if (tid == 0) {
        float m = sred[0];
#pragma unroll
        for (int ww = 1; ww < 8; ww++) m = fmaxf(m, sred[ww]);
        sbc = m;
    }
    __syncthreads();
    mx = sbc;
    __syncthreads();

    float sum = 0.f;
#pragma unroll
    for (int k = 0; k < 16; k++) { v[k] = expf(v[k] - mx); sum += v[k]; }
    float etail = 0.f;
    if (tid == 0) { etail = expf(vtail - mx); sum += etail; }
#pragma unroll
    for (int off = 16; off; off >>= 1) sum += __shfl_xor_sync(0xffffffffu, sum, off);
    if (lane == 0) sred[w] = sum;
    __syncthreads();
    if (tid == 0) {
        float m = 0.f;
#pragma unroll
        for (int ww = 0; ww < 8; ww++) m += sred[ww];
        sbc = m;
    }
    __syncthreads();
    float inv = 1.f / sbc;

    float* pT = g_probsT + (size_t)bh * HW;
    if (tid == 0) {
        g_pcls[bh] = v[0] * inv;                 // s = 0 (CLS)
#pragma unroll
        for (int k = 1; k < 16; k++) pT[k - 1] = v[k] * inv;
        pT[4095] = etail * inv;                  // s = 4096 -> token 4095
    } else {
#pragma unroll
        for (int k = 0; k < 16; k++) pT[base + k - 1] = v[k] * inv;
    }
}

// ---------------- kB: moment GEMM + fused LayerNorm feature-map write -------
// block = (b, 16 d); warp = 2 d; thread = 2 tokens/step; acc packed over the
// s-pair. unroll 4 (smem caps at 2 blocks/SM -> regs free for load batching).
#define SCH 512
__global__ void __launch_bounds__(256) kB(const float* __restrict__ x,
                                          const float* __restrict__ ctx,
                                          const float* __restrict__ gamma,
                                          const float* __restrict__ beta,
                                          float* __restrict__ out) {
    int b   = blockIdx.x >> 6;
    int d0  = (blockIdx.x & 63) * 16;
    int tid = threadIdx.x;
    int w   = tid >> 5, lane = tid & 31;
    int dA  = d0 + w * 2;        // warp owns dA, dA+1

    __shared__ float s_pr[16][SCH + 8];

    u64 acc[16][2];
#pragma unroll
    for (int h = 0; h < 16; h++) { acc[h][0] = 0ull; acc[h][1] = 0ull; }

    const float* xb  = x + (size_t)b * ND * HW;
    const float* pT  = g_probsT + (size_t)b * NHH * HW;
    const float* nmu = g_nmu + b * HW;
    const float* rsv = g_rs  + b * HW;
    float* ob = out + (size_t)b * ND * HW;

    u64 t2A = __ldg(g_t2 + b * ND + dA);
    u64 t2B = __ldg(g_t2 + b * ND + dA + 1);
    float gA = __ldg(gamma + dA), gB = __ldg(gamma + dA + 1);
    float bA = __ldg(beta + dA),  bB = __ldg(beta + dA + 1);
    u64 gdA = pack2(gA, gA), gdB = pack2(gB, gB);
    u64 bdA = pack2(bA, bA), bdB = pack2(bB, bB);

    for (int c = 0; c < HW / SCH; c++) {
        // stage probsT chunk: straight copy, 16 rows x 512 floats
#pragma unroll
        for (int k = 0; k < 8; k++) {
            int idx = k * 256 + tid;          // 0..2047
            int h = idx >> 7, j = idx & 127;
            float4 v = __ldg((const float4*)(pT + (size_t)h * HW + c * SCH) + j);
            *(float4*)&s_pr[h][j * 4] = v;
        }
        __syncthreads();

#pragma unroll 4
        for (int i = 0; i < 8; i++) {
            int sl = i * 64 + lane * 2;
            int p  = c * SCH + sl;
            size_t offA = (size_t)dA * HW + p;
            u64 xcA = add2(ldg2(xb + offA), ldg2(g_pe + offA));
            u64 xcB = add2(ldg2(xb + offA + HW), ldg2(g_pe + offA + HW));

            // fused LayerNorm write for these 2 d x 2 tokens
            u64 nm2 = ldg2(nmu + p);
            u64 rs2 = ldg2(rsv + p);
            u64 AA = mul2(rs2, gdA);
            u64 AB = mul2(rs2, gdB);
            *(u64*)(ob + offA)      = fma2n(add2(add2(xcA, t2A), nm2), AA, bdA);
            *(u64*)(ob + offA + HW) = fma2n(add2(add2(xcB, t2B), nm2), AB, bdB);

#pragma unroll
            for (int h = 0; h < 16; h++) {
                u64 pr2 = *(const u64*)&s_pr[h][sl];
                fma2(acc[h][0], pr2, xcA);
                fma2(acc[h][1], pr2, xcB);
            }
        }
        __syncthreads();
    }

    // cross-lane reduce (disjoint s-subsets per lane)
#pragma unroll
    for (int h = 0; h < 16; h++)
#pragma unroll
        for (int dj = 0; dj < 2; dj++)
#pragma unroll
            for (int off = 16; off; off >>= 1) {
                u64 o = __shfl_xor_sync(0xffffffffu, acc[h][dj], off);
                acc[h][dj] = add2(acc[h][dj], o);
            }

    if (lane == 0) {
        float cv0 = ctx[b * ND + dA], cv1 = ctx[b * ND + dA + 1];
#pragma unroll
        for (int h = 0; h < 16; h++) {
            float pc = g_pcls[b * NHH + h];
            float lo, hi;
            unpack2(acc[h][0], lo, hi);
            g_m[(size_t)(b * NHH + h) * ND + dA]     = lo + hi + pc * cv0;
            unpack2(acc[h][1], lo, hi);
            g_m[(size_t)(b * NHH + h) * ND + dA + 1] = lo + hi + pc * cv1;
        }
    }
}

// ---------------- E1: cls_out = Wv . m + bv ----------
__global__ void __launch_bounds__(256) kE1(const float* __restrict__ Wqkv,
                                           const float* __restrict__ bqkv) {
    int dq   = blockIdx.x * 8 + (threadIdx.x >> 5);
    int lane = threadIdx.x & 31;
    int h    = dq >> 6;
    const float* row = Wqkv + (size_t)(2 * ND + dq) * ND;
    float acc[NB];
#pragma unroll
    for (int b = 0; b < NB; b++) acc[b] = 0.f;
    for (int e = lane; e < ND; e += 32) {
        float wv = row[e];
#pragma unroll
        for (int b = 0; b < NB; b++)
            acc[b] += wv * g_m[(size_t)(b * NHH + h) * ND + e];
    }
#pragma unroll
    for (int b = 0; b < NB; b++) {
#pragma unroll
        for (int off = 16; off; off >>= 1)
            acc[b] += __shfl_xor_sync(0xffffffffu, acc[b], off);
    }
    if (lane == 0) {
        float bias = bqkv[2 * ND + dq];
#pragma unroll
        for (int b = 0; b < NB; b++) g_clsout[b * ND + dq] = acc[b] + bias;
    }
}

// ---------------- E2a: resid = Wo.clsout + bo + ctx ----------
__global__ void __launch_bounds__(256) kE2a(const float* __restrict__ Wo,
                                            const float* __restrict__ bo,
                                            const float* __restrict__ ctx) {
    int d    = blockIdx.x * 8 + (threadIdx.x >> 5);
    int lane = threadIdx.x & 31;
    const float* row = Wo + (size_t)d * ND;
    float acc[NB];
#pragma unroll
    for (int b = 0; b < NB; b++) acc[b] = 0.f;
    for (int e = lane; e < ND; e += 32) {
        float wv = row[e];
#pragma unroll
        for (int b = 0; b < NB; b++) acc[b] += wv * g_clsout[b * ND + e];
    }
#pragma unroll
    for (int b = 0; b < NB; b++) {
#pragma unroll
        for (int off = 16; off; off >>= 1)
            acc[b] += __shfl_xor_sync(0xffffffffu, acc[b], off);
    }
    if (lane == 0) {
        float bias = bo[d];
#pragma unroll
        for (int b = 0; b < NB; b++)
            g_resid[b * ND + d] = acc[b] + bias + ctx[b * ND + d];
    }
}

// ---------------- E2b: LN over resid -> context out ----------
__global__ void __launch_bounds__(256) kE2b(const float* __restrict__ gamma,
                                            const float* __restrict__ beta,
                                            float* __restrict__ out_ctx) {
    int b   = blockIdx.x;
    int tid = threadIdx.x, w = tid >> 5, lane = tid & 31;
    __shared__ float red1[8], red2[8];
    __shared__ float s_mu, s_rs;
    const float* sr = g_resid + b * ND;

    float ls = 0.f, lq = 0.f;
    for (int d = tid; d < ND; d += 256) { float v = sr[d]; ls += v; lq += v * v; }
#pragma unroll
    for (int off = 16; off; off >>= 1) {
        ls += __shfl_xor_sync(0xffffffffu, ls, off);
        lq += __shfl_xor_sync(0xffffffffu, lq, off);
    }
    if (lane == 0) { red1[w] = ls; red2[w] = lq; }
    __syncthreads();
    if (tid == 0) {
        float m = 0.f, q = 0.f;
#pragma unroll
        for (int ww = 0; ww < 8; ww++) { m += red1[ww]; q += red2[ww]; }
        float mu  = m * (1.f / 1024.f);
        float var = q * (1.f / 1024.f) - mu * mu;
        s_mu = mu;
        s_rs = rsqrtf(var + 1e-5f);
    }
    __syncthreads();
    float mu = s_mu, rs = s_rs;
    for (int d = tid; d < ND; d += 256)
        out_ctx[b * ND + d] = (sr[d] - mu) * rs * gamma[d] + beta[d];
}

// ---------------- launch ----------------
extern "C" void kernel_launch(void* const* d_in, const int* in_sizes, int n_in,
                              void* d_out, int out_size) {
    const float* x     = (const float*)d_in[0];
    const float* ctx   = (const float*)d_in[1];
    const float* Wqkv  = (const float*)d_in[2];
    const float* bqkv  = (const float*)d_in[3];
    const float* Wo    = (const float*)d_in[4];
    const float* bo    = (const float*)d_in[5];
    const float* gamma = (const float*)d_in[6];
    const float* beta  = (const float*)d_in[7];
    float* out     = (float*)d_out;
    float* out_ctx = out + (size_t)NB * ND * HW;   // tuple: (feature_map, context)

    kPre<<<ND + 384, 256>>>(Wqkv, bqkv, ctx);
    kP2<<<257, 256>>>(Wqkv, bqkv, Wo, bo);
    kA1<<<dim3(HW / 64, NB), 256>>>(x);
    kSM<<<NB * NHH, 256>>>();
    kB<<<NB * 64, 256>>>(x, ctx, gamma, beta, out);
    kE1<<<128, 256>>>(Wqkv, bqkv);
    kE2a<<<128, 256>>>(Wo, bo, ctx);
    kE2b<<<NB, 256>>>(gamma, beta, out_ctx);
}

// round 17
// speedup vs baseline: 1.3707x; 1.3707x over previous
#include <cuda_runtime.h>
#include <math.h>
#include <float.h>

#define NB   8
#define ND   1024
#define NHH  16
#define HDm  64
#define HW   4096
#define NS   4097   // 1 CLS + 4096 tokens
#define SST  4100   // scores row stride, multiple of 4 -> float4-aligned rows

typedef unsigned long long u64;

// ---------------- packed f32x2 helpers ----------------
__device__ __forceinline__ u64 pack2(float lo, float hi) {
    u64 r; asm("mov.b64 %0, {%1,%2};" : "=l"(r) : "f"(lo), "f"(hi)); return r;
}
__device__ __forceinline__ void unpack2(u64 v, float& lo, float& hi) {
    asm("mov.b64 {%0,%1}, %2;" : "=f"(lo), "=f"(hi) : "l"(v));
}
__device__ __forceinline__ void fma2(u64& d, u64 a, u64 b) {
    asm("fma.rn.f32x2 %0, %1, %2, %0;" : "+l"(d) : "l"(a), "l"(b));
}
__device__ __forceinline__ u64 fma2n(u64 a, u64 b, u64 c) {
    u64 d; asm("fma.rn.f32x2 %0, %1, %2, %3;" : "=l"(d) : "l"(a), "l"(b), "l"(c)); return d;
}
__device__ __forceinline__ u64 add2(u64 a, u64 b) {
    u64 d; asm("add.rn.f32x2 %0, %1, %2;" : "=l"(d) : "l"(a), "l"(b)); return d;
}
__device__ __forceinline__ u64 mul2(u64 a, u64 b) {
    u64 d; asm("mul.rn.f32x2 %0, %1, %2;" : "=l"(d) : "l"(a), "l"(b)); return d;
}
__device__ __forceinline__ u64 ldg2(const float* p) { return __ldg((const u64*)p); }

// ---------------- scratch (device globals; no allocations) ----------------
__device__ float g_pe[ND * HW];           // [d][p] positional encoding (16 MB)
__device__ float g_q0[NB * ND];
__device__ float g_kcls[NB * ND];
__device__ float g_vcls[NB * ND];
__device__ float g_u[NB * ND * NHH];      // [b][d][h]
__device__ u64   g_t2[NB * ND];           // t_b duplicated (t,t)
__device__ float g_ck[NB * NHH];
__device__ float g_scores[NB * NHH * SST];// padded rows (16B-aligned)
__device__ float g_probsT[NB * NHH * HW]; // [b][h][token] (token = s-1)
__device__ float g_pcls[NB * NHH];        // prob of s=0 (CLS)
__device__ float g_nmu[NB * HW];          // -mu per token
__device__ float g_rs[NB * HW];           // rsqrt(var+eps) per token
__device__ float g_m[NB * NHH * ND];
__device__ float g_clsout[NB * ND];
__device__ float g_resid[NB * ND];

// ---------------- kPre: PE table (blocks 0..1023) + P1 GEMV (1024..1407) ----
__global__ void __launch_bounds__(256) kPre(const float* __restrict__ Wqkv,
                                            const float* __restrict__ bqkv,
                                            const float* __restrict__ ctx) {
    int bx = blockIdx.x;
    if (bx < ND) {
        // positional encoding row d: one sincos base per thread + 15 rotations
        int d  = bx;
        int e2 = d & ~1;
        float rate = (float)exp(-(double)e2 * (9.210340371976184 / 1024.0));
        bool iscos = (d & 1);
        int tid = threadIdx.x;
        float s, c, sd, cd;
        sincosf((float)tid * rate, &s, &c);      // base angle
        sincosf(256.f * rate, &sd, &cd);         // step = 256 tokens
        int base = d * HW + tid;
#pragma unroll
        for (int j = 0; j < 16; j++) {
            g_pe[base + j * 256] = iscos ? c : s;
            float s2 = fmaf(s, cd, c * sd);
            float c2 = fmaf(c, cd, -s * sd);
            s = s2; c = c2;
        }
    } else {
        // P1: q0 / k_cls / v_cls (warp per Wqkv row, float4 loads)
        int gw   = (bx - ND) * 8 + (threadIdx.x >> 5);
        int lane = threadIdx.x & 31;
        if (gw >= 3 * ND) return;
        const float4* row4 = (const float4*)(Wqkv + (size_t)gw * ND);
        const float4* ctx4 = (const float4*)ctx;
        float acc[NB];
#pragma unroll
        for (int b = 0; b < NB; b++) acc[b] = 0.f;
#pragma unroll
        for (int e4 = lane; e4 < ND / 4; e4 += 32) {
            float4 wv = __ldg(row4 + e4);
#pragma unroll
            for (int b = 0; b < NB; b++) {
                float4 cv = __ldg(ctx4 + b * (ND / 4) + e4);
                acc[b] += wv.x * cv.x + wv.y * cv.y + wv.z * cv.z + wv.w * cv.w;
            }
        }
#pragma unroll
        for (int b = 0; b < NB; b++) {
#pragma unroll
            for (int off = 16; off; off >>= 1)
                acc[b] += __shfl_xor_sync(0xffffffffu, acc[b], off);
        }
        if (lane == 0) {
            float bias = bqkv[gw];
            float* dst;
            if (gw < ND)            dst = g_q0   + gw;
            else if (gw < 2 * ND)   dst = g_kcls + (gw - ND);
            else                    dst = g_vcls + (gw - 2 * ND);
#pragma unroll
            for (int b = 0; b < NB; b++) dst[b * ND] = acc[b] + bias;
        }
    }
}

// ---------------- P2: u (128 blocks), t2 (128 blocks), ck (1 block) ---------
__global__ void __launch_bounds__(256) kP2(const float* __restrict__ Wqkv,
                                           const float* __restrict__ bqkv,
                                           const float* __restrict__ Wo,
                                           const float* __restrict__ bo) {
    int bx = blockIdx.x;
    if (bx < 128) {
        int h   = bx >> 3;
        int dsl = bx & 7;
        __shared__ float s_q[NB * HDm];
        for (int i = threadIdx.x; i < NB * HDm; i += blockDim.x) {
            int b = i >> 6, j = i & 63;
            s_q[i] = g_q0[b * ND + h * HDm + j];
        }
        __syncthreads();
        if (threadIdx.x < 128) {
            int d = dsl * 128 + threadIdx.x;
            float acc[NB];
#pragma unroll
            for (int b = 0; b < NB; b++) acc[b] = 0.f;
#pragma unroll 4
            for (int j = 0; j < HDm; j++) {
                float wv = __ldg(Wqkv + (size_t)(ND + h * HDm + j) * ND + d);
#pragma unroll
                for (int b = 0; b < NB; b++) acc[b] += s_q[b * HDm + j] * wv;
            }
#pragma unroll
            for (int b = 0; b < NB; b++)
                g_u[(size_t)(b * ND + d) * NHH + h] = acc[b];
        }
    } else if (bx < 256) {
        // t2: warp per Wo row, float4 loads
        int d    = (bx - 128) * 8 + (threadIdx.x >> 5);
        int lane = threadIdx.x & 31;
        const float4* row4 = (const float4*)(Wo + (size_t)d * ND);
        const float4* vc4  = (const float4*)g_vcls;
        float acc[NB];
#pragma unroll
        for (int b = 0; b < NB; b++) acc[b] = 0.f;
#pragma unroll
        for (int e4 = lane; e4 < ND / 4; e4 += 32) {
            float4 wv = __ldg(row4 + e4);
#pragma unroll
            for (int b = 0; b < NB; b++) {
                float4 cv = __ldg(vc4 + b * (ND / 4) + e4);
                acc[b] += wv.x * cv.x + wv.y * cv.y + wv.z * cv.z + wv.w * cv.w;
            }
        }
#pragma unroll
        for (int b = 0; b < NB; b++) {
#pragma unroll
            for (int off = 16; off; off >>= 1)
                acc[b] += __shfl_xor_sync(0xffffffffu, acc[b], off);
        }
        if (lane == 0) {
            float bias = bo[d];
#pragma unroll
            for (int b = 0; b < NB; b++) {
                float v = acc[b] + bias;
                g_t2[b * ND + d] = pack2(v, v);
            }
        }
    } else {
        int t = threadIdx.x;
        if (t < NB * NHH) {
            int b = t >> 4, h = t & 15;
            float ck = 0.f, s0 = 0.f;
            for (int j = 0; j < HDm; j++) {
                float q = g_q0[b * ND + h * HDm + j];
                ck += q * bqkv[ND + h * HDm + j];
                s0 += q * g_kcls[b * ND + h * HDm + j];
            }
            g_ck[t] = ck;
            g_scores[(size_t)t * SST] = s0 * 0.125f;
        }
    }
}

// ---------------- kA1: scores + LayerNorm statistics (R15 known-good) ------
// block = (b, 64 tokens). 8 warps; warp w handles d = 8i+w; thread = 2 tokens.
__global__ void __launch_bounds__(256) kA1(const float* __restrict__ x) {
    int b    = blockIdx.y;
    int p0   = blockIdx.x * 64;
    int tid  = threadIdx.x;
    int w    = tid >> 5;
    int lane = tid & 31;
    int p    = p0 + lane * 2;

    __shared__ float s_acc[8][64][18];   // [warp][token][head], padded
    __shared__ float s_sum[8][64];
    __shared__ float s_sq[8][64];

    const float* xb = x   + (size_t)b * ND * HW;
    const u64*   tb = g_t2 + b * ND;
    const u64*   ub = (const u64*)(g_u + (size_t)b * ND * NHH);

    u64 acc0[8], acc1[8];   // [head-pair] for token0 / token1
#pragma unroll
    for (int i = 0; i < 8; i++) { acc0[i] = 0ull; acc1[i] = 0ull; }
    u64 lsum = 0ull, lsq = 0ull;

#pragma unroll 2
    for (int i = 0; i < 128; i++) {
        int d = i * 8 + w;
        size_t off = (size_t)d * HW + p;
        u64 xc2 = add2(ldg2(xb + off), ldg2(g_pe + off));
        u64 r2  = add2(xc2, __ldg(tb + d));
        lsum = add2(lsum, r2);
        fma2(lsq, r2, r2);
        float xl, xh; unpack2(xc2, xl, xh);
        u64 xll = pack2(xl, xl), xhh = pack2(xh, xh);
        const ulonglong2* uu = (const ulonglong2*)(ub + (size_t)d * 8);
#pragma unroll
        for (int q = 0; q < 4; q++) {
            ulonglong2 u2 = __ldg(uu + q);
            fma2(acc0[2 * q],     u2.x, xll);
            fma2(acc0[2 * q + 1], u2.y, xll);
            fma2(acc1[2 * q],     u2.x, xhh);
            fma2(acc1[2 * q + 1], u2.y, xhh);
        }
    }

#pragma unroll
    for (int hp = 0; hp < 8; hp++) {
        *(u64*)&s_acc[w][lane * 2][hp * 2]     = acc0[hp];
        *(u64*)&s_acc[w][lane * 2 + 1][hp * 2] = acc1[hp];
    }
    {
        float a, c;
        unpack2(lsum, a, c); s_sum[w][lane * 2] = a; s_sum[w][lane * 2 + 1] = c;
        unpack2(lsq,  a, c); s_sq[w][lane * 2]  = a; s_sq[w][lane * 2 + 1]  = c;
    }
    __syncthreads();

    if (tid < 64) {
        float m = 0.f, q = 0.f;
#pragma unroll
        for (int ww = 0; ww < 8; ww++) { m += s_sum[ww][tid]; q += s_sq[ww][tid]; }
        float mu  = m * (1.f / 1024.f);
        float var = q * (1.f / 1024.f) - mu * mu;
        g_nmu[b * HW + p0 + tid] = -mu;
        g_rs[b * HW + p0 + tid]  = rsqrtf(var + 1e-5f);
    }
    // scores: 1024 (h,tok) pairs
#pragma unroll
    for (int r = 0; r < 4; r++) {
        int idx = r * 256 + tid;
        int h = idx >> 6, tok = idx & 63;
        float sc = 0.f;
#pragma unroll
        for (int ww = 0; ww < 8; ww++) sc += s_acc[ww][tok][h];
        sc = (sc + __ldg(g_ck + b * NHH + h)) * 0.125f;
        g_scores[(size_t)(b * NHH + h) * SST + (p0 + tok + 1)] = sc;
    }
}

// ---------------- Softmax (row = (b,h), len 4097) -> probsT [b][h][token] ---
// Register-resident: one global read, no expf recompute.
__global__ void __launch_bounds__(256) kSM() {
    int bh = blockIdx.x;
    const float* sc = g_scores + (size_t)bh * SST;   // 16B-aligned row
    __shared__ float sred[8];
    __shared__ float sbc;
    int tid = threadIdx.x, w = tid >> 5, lane = tid & 31;

    // thread t holds s = t*16 .. t*16+15 (4 x LDG.128); tid 0 also handles s=4096
    float v[16];
    int base = tid * 16;
#pragma unroll
    for (int k = 0; k < 4; k++) {
        float4 q = __ldg((const float4*)(sc + base) + k);
        v[k * 4 + 0] = q.x; v[k * 4 + 1] = q.y; v[k * 4 + 2] = q.z; v[k * 4 + 3] = q.w;
    }
    float vtail = (tid == 0) ? sc[4096] : -FLT_MAX;

    float mx = vtail;
#pragma unroll
    for (int k = 0; k < 16; k++) mx = fmaxf(mx, v[k]);
#pragma unroll
    for (int off = 16; off; off >>= 1) mx = fmaxf(mx, __shfl_xor_sync(0xffffffffu, mx, off));
    if (lane == 0) sred[w] = mx;
    __syncthreads();
    if (tid == 0) {
        float m = sred[0];
#pragma unroll
        for (int ww = 1; ww < 8; ww++) m = fmaxf(m, sred[ww]);
        sbc = m;
    }
    __syncthreads();
    mx = sbc;
    __syncthreads();

    float sum = 0.f;
#pragma unroll
    for (int k = 0; k < 16; k++) { v[k] = expf(v[k] - mx); sum += v[k]; }
    float etail = 0.f;
    if (tid == 0) { etail = expf(vtail - mx); sum += etail; }
#pragma unroll
    for (int off = 16; off; off >>= 1) sum += __shfl_xor_sync(0xffffffffu, sum, off);
    if (lane == 0) sred[w] = sum;
    __syncthreads();
    if (tid == 0) {
        float m = 0.f;
#pragma unroll
        for (int ww = 0; ww < 8; ww++) m += sred[ww];
        sbc = m;
    }
    __syncthreads();
    float inv = 1.f / sbc;

    float* pT = g_probsT + (size_t)bh * HW;
    if (tid == 0) {
        g_pcls[bh] = v[0] * inv;                 // s = 0 (CLS)
#pragma unroll
        for (int k = 1; k < 16; k++) pT[k - 1] = v[k] * inv;
        pT[4095] = etail * inv;                  // s = 4096 -> token 4095
    } else {
#pragma unroll
        for (int k = 0; k < 16; k++) pT[base + k - 1] = v[k] * inv;
    }
}

// ---------------- kB: moment GEMM + fused LayerNorm write (R15 known-good) --
#define SCH 512
__global__ void __launch_bounds__(256) kB(const float* __restrict__ x,
                                          const float* __restrict__ ctx,
                                          const float* __restrict__ gamma,
                                          const float* __restrict__ beta,
                                          float* __restrict__ out) {
    int b   = blockIdx.x >> 6;
    int d0  = (blockIdx.x & 63) * 16;
    int tid = threadIdx.x;
    int w   = tid >> 5, lane = tid & 31;
    int dA  = d0 + w * 2;        // warp owns dA, dA+1

    __shared__ float s_pr[16][SCH + 8];

    u64 acc[16][2];
#pragma unroll
    for (int h = 0; h < 16; h++) { acc[h][0] = 0ull; acc[h][1] = 0ull; }

    const float* xb  = x + (size_t)b * ND * HW;
    const float* pT  = g_probsT + (size_t)b * NHH * HW;
    const float* nmu = g_nmu + b * HW;
    const float* rsv = g_rs  + b * HW;
    float* ob = out + (size_t)b * ND * HW;

    u64 t2A = __ldg(g_t2 + b * ND + dA);
    u64 t2B = __ldg(g_t2 + b * ND + dA + 1);
    float gA = __ldg(gamma + dA), gB = __ldg(gamma + dA + 1);
    float bA = __ldg(beta + dA),  bB = __ldg(beta + dA + 1);
    u64 gdA = pack2(gA, gA), gdB = pack2(gB, gB);
    u64 bdA = pack2(bA, bA), bdB = pack2(bB, bB);

    for (int c = 0; c < HW / SCH; c++) {
        // stage probsT chunk: straight copy, 16 rows x 512 floats
#pragma unroll
        for (int k = 0; k < 8; k++) {
            int idx = k * 256 + tid;          // 0..2047
            int h = idx >> 7, j = idx & 127;
            float4 v = __ldg((const float4*)(pT + (size_t)h * HW + c * SCH) + j);
            *(float4*)&s_pr[h][j * 4] = v;
        }
        __syncthreads();

#pragma unroll 2
        for (int i = 0; i < 8; i++) {
            int sl = i * 64 + lane * 2;
            int p  = c * SCH + sl;
            size_t offA = (size_t)dA * HW + p;
            u64 xcA = add2(ldg2(xb + offA), ldg2(g_pe + offA));
            u64 xcB = add2(ldg2(xb + offA + HW), ldg2(g_pe + offA + HW));

            // fused LayerNorm write for these 2 d x 2 tokens
            u64 nm2 = ldg2(nmu + p);
            u64 rs2 = ldg2(rsv + p);
            u64 AA = mul2(rs2, gdA);
            u64 AB = mul2(rs2, gdB);
            *(u64*)(ob + offA)      = fma2n(add2(add2(xcA, t2A), nm2), AA, bdA);
            *(u64*)(ob + offA + HW) = fma2n(add2(add2(xcB, t2B), nm2), AB, bdB);

#pragma unroll
            for (int h = 0; h < 16; h++) {
                u64 pr2 = *(const u64*)&s_pr[h][sl];
                fma2(acc[h][0], pr2, xcA);
                fma2(acc[h][1], pr2, xcB);
            }
        }
        __syncthreads();
    }

    // cross-lane reduce (disjoint s-subsets per lane)
#pragma unroll
    for (int h = 0; h < 16; h++)
#pragma unroll
        for (int dj = 0; dj < 2; dj++)
#pragma unroll
            for (int off = 16; off; off >>= 1) {
                u64 o = __shfl_xor_sync(0xffffffffu, acc[h][dj], off);
                acc[h][dj] = add2(acc[h][dj], o);
            }

    if (lane == 0) {
        float cv0 = ctx[b * ND + dA], cv1 = ctx[b * ND + dA + 1];
#pragma unroll
        for (int h = 0; h < 16; h++) {
            float pc = g_pcls[b * NHH + h];
            float lo, hi;
            unpack2(acc[h][0], lo, hi);
            g_m[(size_t)(b * NHH + h) * ND + dA]     = lo + hi + pc * cv0;
            unpack2(acc[h][1], lo, hi);
            g_m[(size_t)(b * NHH + h) * ND + dA + 1] = lo + hi + pc * cv1;
        }
    }
}

// ---------------- E1: cls_out = Wv . m + bv (float4 loads) ----------
__global__ void __launch_bounds__(256) kE1(const float* __restrict__ Wqkv,
                                           const float* __restrict__ bqkv) {
    int dq   = blockIdx.x * 8 + (threadIdx.x >> 5);
    int lane = threadIdx.x & 31;
    int h    = dq >> 6;
    const float4* row4 = (const float4*)(Wqkv + (size_t)(2 * ND + dq) * ND);
    float acc[NB];
#pragma unroll
    for (int b = 0; b < NB; b++) acc[b] = 0.f;
#pragma unroll
    for (int e4 = lane; e4 < ND / 4; e4 += 32) {
        float4 wv = __ldg(row4 + e4);
#pragma unroll
        for (int b = 0; b < NB; b++) {
            float4 mv = __ldg((const float4*)(g_m + (size_t)(b * NHH + h) * ND) + e4);
            acc[b] += wv.x * mv.x + wv.y * mv.y + wv.z * mv.z + wv.w * mv.w;
        }
    }
#pragma unroll
    for (int b = 0; b < NB; b++) {
#pragma unroll
        for (int off = 16; off; off >>= 1)
            acc[b] += __shfl_xor_sync(0xffffffffu, acc[b], off);
    }
    if (lane == 0) {
        float bias = bqkv[2 * ND + dq];
#pragma unroll
        for (int b = 0; b < NB; b++) g_clsout[b * ND + dq] = acc[b] + bias;
    }
}

// ---------------- E2a: resid = Wo.clsout + bo + ctx (float4 loads) ----------
__global__ void __launch_bounds__(256) kE2a(const float* __restrict__ Wo,
                                            const float* __restrict__ bo,
                                            const float* __restrict__ ctx) {
    int d    = blockIdx.x * 8 + (threadIdx.x >> 5);
    int lane = threadIdx.x & 31;
    const float4* row4 = (const float4*)(Wo + (size_t)d * ND);
    const float4* cl4  = (const float4*)g_clsout;
    float acc[NB];
#pragma unroll
    for (int b = 0; b < NB; b++) acc[b] = 0.f;
#pragma unroll
    for (int e4 = lane; e4 < ND / 4; e4 += 32) {
        float4 wv = __ldg(row4 + e4);
#pragma unroll
        for (int b = 0; b < NB; b++) {
            float4 cv = __ldg(cl4 + b * (ND / 4) + e4);
            acc[b] += wv.x * cv.x + wv.y * cv.y + wv.z * cv.z + wv.w * cv.w;
        }
    }
#pragma unroll
    for (int b = 0; b < NB; b++) {
#pragma unroll
        for (int off = 16; off; off >>= 1)
            acc[b] += __shfl_xor_sync(0xffffffffu, acc[b], off);
    }
    if (lane == 0) {
        float bias = bo[d];
#pragma unroll
        for (int b = 0; b < NB; b++)
            g_resid[b * ND + d] = acc[b] + bias + ctx[b * ND + d];
    }
}

// ---------------- E2b: LN over resid -> context out ----------
__global__ void __launch_bounds__(256) kE2b(const float* __restrict__ gamma,
                                            const float* __restrict__ beta,
                                            float* __restrict__ out_ctx) {
    int b   = blockIdx.x;
    int tid = threadIdx.x, w = tid >> 5, lane = tid & 31;
    __shared__ float red1[8], red2[8];
    __shared__ float s_mu, s_rs;
    const float* sr = g_resid + b * ND;

    float ls = 0.f, lq = 0.f;
    for (int d = tid; d < ND; d += 256) { float v = sr[d]; ls += v; lq += v * v; }
#pragma unroll
    for (int off = 16; off; off >>= 1) {
        ls += __shfl_xor_sync(0xffffffffu, ls, off);
        lq += __shfl_xor_sync(0xffffffffu, lq, off);
    }
    if (lane == 0) { red1[w] = ls; red2[w] = lq; }
    __syncthreads();
    if (tid == 0) {
        float m = 0.f, q = 0.f;
#pragma unroll
        for (int ww = 0; ww < 8; ww++) { m += red1[ww]; q += red2[ww]; }
        float mu  = m * (1.f / 1024.f);
        float var = q * (1.f / 1024.f) - mu * mu;
        s_mu = mu;
        s_rs = rsqrtf(var + 1e-5f);
    }
    __syncthreads();
    float mu = s_mu, rs = s_rs;
    for (int d = tid; d < ND; d += 256)
        out_ctx[b * ND + d] = (sr[d] - mu) * rs * gamma[d] + beta[d];
}

// ---------------- launch ----------------
extern "C" void kernel_launch(void* const* d_in, const int* in_sizes, int n_in,
                              void* d_out, int out_size) {
    const float* x     = (const float*)d_in[0];
    const float* ctx   = (const float*)d_in[1];
    const float* Wqkv  = (const float*)d_in[2];
    const float* bqkv  = (const float*)d_in[3];
    const float* Wo    = (const float*)d_in[4];
    const float* bo    = (const float*)d_in[5];
    const float* gamma = (const float*)d_in[6];
    const float* beta  = (const float*)d_in[7];
    float* out     = (float*)d_out;
    float* out_ctx = out + (size_t)NB * ND * HW;   // tuple: (feature_map, context)

    kPre<<<ND + 384, 256>>>(Wqkv, bqkv, ctx);
    kP2<<<257, 256>>>(Wqkv, bqkv, Wo, bo);
    kA1<<<dim3(HW / 64, NB), 256>>>(x);
    kSM<<<NB * NHH, 256>>>();
    kB<<<NB * 64, 256>>>(x, ctx, gamma, beta, out);
    kE1<<<128, 256>>>(Wqkv, bqkv);
    kE2a<<<128, 256>>>(Wo, bo, ctx);
    kE2b<<<NB, 256>>>(gamma, beta, out_ctx);
}